// round 16
// baseline (speedup 1.0000x reference)
#include <cuda_runtime.h>
#include <cuda_bf16.h>
#include <cstdint>

#define Nn 50000
#define Hh 128
#define Ee 500000

// fused prep kernel block ranges
#define PB_BUILD  1954                 // ceil(Ee/256)
#define PB_XSPLIT 3125                 // Nn*64/4/256
#define PB_WPREP  192                  // 3*16384/256
#define PB_TOTAL  (PB_BUILD + PB_XSPLIT + PB_WPREP)

typedef unsigned long long u64;
typedef unsigned int u32;

// ---------------------------------------------------------------------------
// Scratch (device globals: no allocation allowed)
// ---------------------------------------------------------------------------
__device__ int g_head[Nn];
__device__ u64 g_link[Ee];
__device__ u32 g_ah[(size_t)Nn * 64];   // aggr hi
__device__ u32 g_al[(size_t)Nn * 64];   // aggr lo
__device__ u32 g_xh[(size_t)Nn * 64];   // x_a hi
__device__ u32 g_xl[(size_t)Nn * 64];   // x_a lo
__device__ u32 g_h1h[(size_t)Nn * 64];  // h1 hi
__device__ u32 g_h1l[(size_t)Nn * 64];  // h1 lo
// Weights, TRANSPOSED row-major: Wt[k*128 + n] = W[n][k]. 0=Wl, 1=W0+W1, 2=Wout
__device__ unsigned short g_wt_hi[3][16384];
__device__ unsigned short g_wt_lo[3][16384];

// ---------------------------------------------------------------------------
// helpers
// ---------------------------------------------------------------------------
__device__ __forceinline__ u32 smem_u32(const void* p) {
    u32 a;
    asm("{ .reg .u64 t; cvta.to.shared.u64 t, %1; cvt.u32.u64 %0, t; }"
        : "=r"(a) : "l"(p));
    return a;
}
__device__ __forceinline__ void split2(float a, float b, u32& hi, u32& lo) {
    __nv_bfloat16 ha = __float2bfloat16(a), hb = __float2bfloat16(b);
    hi = (u32)__bfloat16_as_ushort(ha) | ((u32)__bfloat16_as_ushort(hb) << 16);
    __nv_bfloat16 la = __float2bfloat16(a - __bfloat162float(ha));
    __nv_bfloat16 lb = __float2bfloat16(b - __bfloat162float(hb));
    lo = (u32)__bfloat16_as_ushort(la) | ((u32)__bfloat16_as_ushort(lb) << 16);
}

#define LDMX4(r, addr) \
    asm volatile("ldmatrix.sync.aligned.m8n8.x4.shared.b16 {%0,%1,%2,%3}, [%4];" \
        : "=r"((r)[0]), "=r"((r)[1]), "=r"((r)[2]), "=r"((r)[3]) : "r"(addr))
#define LDMX4T(r, addr) \
    asm volatile("ldmatrix.sync.aligned.m8n8.x4.trans.shared.b16 {%0,%1,%2,%3}, [%4];" \
        : "=r"((r)[0]), "=r"((r)[1]), "=r"((r)[2]), "=r"((r)[3]) : "r"(addr))
#define MMA(c, a, b0, b1) \
    asm volatile("mma.sync.aligned.m16n8k16.row.col.f32.bf16.bf16.f32 " \
        "{%0,%1,%2,%3},{%4,%5,%6,%7},{%8,%9},{%0,%1,%2,%3};" \
        : "+f"((c)[0]), "+f"((c)[1]), "+f"((c)[2]), "+f"((c)[3]) \
        : "r"((a)[0]), "r"((a)[1]), "r"((a)[2]), "r"((a)[3]), "r"(b0), "r"(b1))
#define CPA16(dst, src) \
    asm volatile("cp.async.ca.shared.global [%0], [%1], 16;" \
                 :: "r"((u32)(dst)), "l"(src) : "memory")
#define CPA_COMMIT() asm volatile("cp.async.commit_group;" ::: "memory")
#define CPA_WAIT0()  asm volatile("cp.async.wait_group 0;" ::: "memory")

// ---------------------------------------------------------------------------
// Fused prep: build linked list ∥ split x_a ∥ weight transpose+split.
// ---------------------------------------------------------------------------
__global__ void prep_kernel(const int* __restrict__ edge,
                            const float* __restrict__ x,
                            const float* __restrict__ wl,
                            const float* __restrict__ w0,
                            const float* __restrict__ w1,
                            const float* __restrict__ wout) {
    int b = blockIdx.x;
    int tid = threadIdx.x;
    if (b < PB_BUILD) {
        int e = b * 256 + tid;
        if (e < Ee) {
            int dst = __ldg(edge + e);
            int src = __ldg(edge + Ee + e);
            int prev = atomicExch(&g_head[dst], e);
            g_link[e] = ((u64)(unsigned)src << 32) | (unsigned)prev;
        }
    } else if (b < PB_BUILD + PB_XSPLIT) {
        size_t t = (size_t)(b - PB_BUILD) * 256 + tid;
        const float4* xp = reinterpret_cast<const float4*>(x) + t * 2;
        float4 v0 = __ldg(xp);
        float4 v1 = __ldg(xp + 1);
        uint4 h, l;
        split2(v0.x, v0.y, h.x, l.x);
        split2(v0.z, v0.w, h.y, l.y);
        split2(v1.x, v1.y, h.z, l.z);
        split2(v1.z, v1.w, h.w, l.w);
        reinterpret_cast<uint4*>(g_xh)[t] = h;
        reinterpret_cast<uint4*>(g_xl)[t] = l;
    } else {
        int i = (b - PB_BUILD - PB_XSPLIT) * 256 + tid;
        int mat = i >> 14;
        int l = i & 16383;
        int k = l >> 7, n = l & 127;
        int src = n * 128 + k;
        float v = (mat == 0) ? __ldg(wl + src)
                : (mat == 1) ? __ldg(w0 + src) + __ldg(w1 + src)
                             : __ldg(wout + src);
        __nv_bfloat16 hb = __float2bfloat16(v);
        g_wt_hi[mat][l] = __bfloat16_as_ushort(hb);
        g_wt_lo[mat][l] =
            __bfloat16_as_ushort(__float2bfloat16(v - __bfloat162float(hb)));
    }
}

// ---------------------------------------------------------------------------
// Gather-reduce: FOUR nodes per warp, interleaved chains (4x chain MLP).
// Per-chain guards are warp-uniform (chain state identical across lanes).
// grid 1563 x 8 warps x 4 nodes >= 50000, bounds-guarded.
// ---------------------------------------------------------------------------
__global__ void aggregate_kernel(const float* __restrict__ x) {
    int nb = (blockIdx.x * 8 + (threadIdx.x >> 5)) * 4;
    int lane = threadIdx.x & 31;
    if (nb >= Nn) return;

    float4 acc[4];
    int e[4];
    #pragma unroll
    for (int j = 0; j < 4; j++) {
        acc[j] = make_float4(0.f, 0.f, 0.f, 0.f);
        e[j] = (nb + j < Nn) ? g_head[nb + j] : -1;
    }

    while ((e[0] & e[1] & e[2] & e[3]) != -1) {   // any chain active
        #pragma unroll
        for (int j = 0; j < 4; j++) {
            if (e[j] != -1) {
                u64 pk = __ldg(g_link + e[j]);
                int src = (int)(pk >> 32);
                e[j] = (int)(unsigned)pk;
                float4 v = *reinterpret_cast<const float4*>(
                    x + (size_t)src * Hh + lane * 4);
                acc[j].x += v.x; acc[j].y += v.y;
                acc[j].z += v.z; acc[j].w += v.w;
            }
        }
    }

    #pragma unroll
    for (int j = 0; j < 4; j++) {
        if (nb + j < Nn) {
            u32 h0, l0, h1, l1;
            split2(acc[j].x, acc[j].y, h0, l0);
            split2(acc[j].z, acc[j].w, h1, l1);
            size_t o = (size_t)(nb + j) * 64 + lane * 2;
            g_ah[o] = h0; g_ah[o + 1] = h1;
            g_al[o] = l0; g_al[o + 1] = l1;
        }
    }
}

// ---------------------------------------------------------------------------
// Tensor-core GEMM (R13 pipeline: k16 chunks, cp.async double-buffered A,
// W resident per segment).
//   C[M,128] = act( sum_seg A_seg @ W_seg^T + bias )
// 256 threads = 8 warps (warp tile 32m x 64n), 128x128 block tile.
// mode 1: relu, write split bf16 h1.  mode 0: write fp32 + bias.
// ---------------------------------------------------------------------------
#define SMB_BIAS 0        // 512 B
#define SMB_A0   512      // buf0: hi 6144 + lo 6144
#define SMB_A1   12800    // buf1
#define SMB_WH   25088    // 128 x 272
#define SMB_WL   59904
#define SMB_TOT  94720
#define APITCH   48
#define ABUF_LO  6144
#define WPITCH   272

__global__ __launch_bounds__(256, 2) void tc_gemm(
    const u32* __restrict__ A0h, const u32* __restrict__ A0l,
    const u32* __restrict__ A1h, const u32* __restrict__ A1l,
    int mat0, int mat1, int nseg,
    const float* __restrict__ ba, const float* __restrict__ bb,
    const float* __restrict__ bc,
    float* __restrict__ outf, u32* __restrict__ outh, u32* __restrict__ outl,
    int mode, int M)
{
    extern __shared__ __align__(16) char smem[];
    const u32 sb = smem_u32(smem);
    float* bias_s = reinterpret_cast<float*>(smem + SMB_BIAS);

    const int tid = threadIdx.x;
    const int w = tid >> 5, lane = tid & 31;
    const int mw = (w & 3) * 32, nw = (w >> 2) * 64;
    const int bm = blockIdx.x * 128;

    if (bm + 128 > M) {
        #pragma unroll
        for (int q = 0; q < 6; q++)
            reinterpret_cast<uint4*>(smem + SMB_A0)[q * 256 + tid] =
                make_uint4(0, 0, 0, 0);
    }
    if (tid < 128) {
        float s = __ldg(ba + tid);
        if (bb) s += __ldg(bb + tid);
        if (bc) s += __ldg(bc + tid);
        bias_s[tid] = s;
    }

    const u32 aoff = (u32)((mw + (lane & 15)) * APITCH + (lane >> 4) * 16);
    const int wg = lane >> 3, wi = lane & 7;
    const u32 wkoff = (u32)(((wg & 1) * 8 + wi) * WPITCH);
    const u32 wnoff = (u32)((nw + (wg >> 1) * 8) * 2);

    const int ar = tid >> 1, ahalf = tid & 1;
    const bool avalid = (bm + ar) < M;
    const u32 adst_off = (u32)(ar * APITCH + ahalf * 16);

    float c[2][8][4];
    #pragma unroll
    for (int mg = 0; mg < 2; mg++)
        #pragma unroll
        for (int nf = 0; nf < 8; nf++)
            #pragma unroll
            for (int q = 0; q < 4; q++) c[mg][nf][q] = 0.f;

    #pragma unroll 1
    for (int seg = 0; seg < nseg; seg++) {
        const u32* Ah = seg ? A1h : A0h;
        const u32* Al = seg ? A1l : A0l;
        const int mat = seg ? mat1 : mat0;

        __syncthreads();

        {   // async stage W hi/lo (full segment)
            const char* sh = reinterpret_cast<const char*>(g_wt_hi[mat]);
            const char* sl = reinterpret_cast<const char*>(g_wt_lo[mat]);
            #pragma unroll
            for (int q = 0; q < 8; q++) {
                int u = q * 256 + tid;
                int kk = u >> 4, c16 = u & 15;
                u32 d = (u32)(kk * WPITCH + c16 * 16);
                CPA16(sb + SMB_WH + d, sh + (size_t)u * 16);
                CPA16(sb + SMB_WL + d, sl + (size_t)u * 16);
            }
        }
        if (avalid) {
            size_t su = (size_t)(bm + ar) * 16 + ahalf;
            CPA16(sb + SMB_A0 + adst_off,
                  reinterpret_cast<const char*>(Ah) + su * 16);
            CPA16(sb + SMB_A0 + ABUF_LO + adst_off,
                  reinterpret_cast<const char*>(Al) + su * 16);
        }
        CPA_COMMIT();

        #pragma unroll 1
        for (int kc = 0; kc < 8; kc++) {
            CPA_WAIT0();
            __syncthreads();

            if (kc < 7) {
                u32 dstb = sb + (((kc + 1) & 1) ? SMB_A1 : SMB_A0);
                if (avalid) {
                    size_t su = (size_t)(bm + ar) * 16 + (kc + 1) * 2 + ahalf;
                    CPA16(dstb + adst_off,
                          reinterpret_cast<const char*>(Ah) + su * 16);
                    CPA16(dstb + ABUF_LO + adst_off,
                          reinterpret_cast<const char*>(Al) + su * 16);
                }
                CPA_COMMIT();
            }

            const u32 abase = sb + ((kc & 1) ? SMB_A1 : SMB_A0);
            u32 ah[2][4], al_[2][4];
            #pragma unroll
            for (int mg = 0; mg < 2; mg++) {
                LDMX4(ah[mg],  abase + aoff + mg * 16 * APITCH);
                LDMX4(al_[mg], abase + ABUF_LO + aoff + mg * 16 * APITCH);
            }
            u32 bw[4][4];
            const u32 wko = (u32)(kc * 16 * WPITCH) + wkoff;
            #pragma unroll
            for (int nf = 0; nf < 4; nf++)
                LDMX4T(bw[nf], sb + SMB_WH + wko + wnoff + nf * 32);
            #pragma unroll
            for (int mg = 0; mg < 2; mg++)
                #pragma unroll
                for (int nf = 0; nf < 4; nf++) {
                    MMA(c[mg][2 * nf],     ah[mg],  bw[nf][0], bw[nf][1]);
                    MMA(c[mg][2 * nf + 1], ah[mg],  bw[nf][2], bw[nf][3]);
                    MMA(c[mg][2 * nf],     al_[mg], bw[nf][0], bw[nf][1]);
                    MMA(c[mg][2 * nf + 1], al_[mg], bw[nf][2], bw[nf][3]);
                }
            #pragma unroll
            for (int nf = 0; nf < 4; nf++)
                LDMX4T(bw[nf], sb + SMB_WL + wko + wnoff + nf * 32);
            #pragma unroll
            for (int mg = 0; mg < 2; mg++)
                #pragma unroll
                for (int nf = 0; nf < 4; nf++) {
                    MMA(c[mg][2 * nf],     ah[mg], bw[nf][0], bw[nf][1]);
                    MMA(c[mg][2 * nf + 1], ah[mg], bw[nf][2], bw[nf][3]);
                }
        }
    }

    // ---- epilogue ----
    const int r0 = (lane >> 2);
    const int cb = 2 * (lane & 3);
    #pragma unroll
    for (int mg = 0; mg < 2; mg++) {
        #pragma unroll
        for (int nf = 0; nf < 8; nf++) {
            int col = nw + nf * 8 + cb;
            int rowA = bm + mw + mg * 16 + r0;
            int rowB = rowA + 8;
            float b0 = bias_s[col], b1 = bias_s[col + 1];
            if (mode) {
                float h00 = fmaxf(c[mg][nf][0] + b0, 0.f);
                float h01 = fmaxf(c[mg][nf][1] + b1, 0.f);
                float h10 = fmaxf(c[mg][nf][2] + b0, 0.f);
                float h11 = fmaxf(c[mg][nf][3] + b1, 0.f);
                u32 hi, lo;
                if (rowA < M) {
                    split2(h00, h01, hi, lo);
                    outh[(size_t)rowA * 64 + (col >> 1)] = hi;
                    outl[(size_t)rowA * 64 + (col >> 1)] = lo;
                }
                if (rowB < M) {
                    split2(h10, h11, hi, lo);
                    outh[(size_t)rowB * 64 + (col >> 1)] = hi;
                    outl[(size_t)rowB * 64 + (col >> 1)] = lo;
                }
            } else {
                if (rowA < M)
                    *reinterpret_cast<float2*>(outf + (size_t)rowA * 128 + col) =
                        make_float2(c[mg][nf][0] + b0, c[mg][nf][1] + b1);
                if (rowB < M)
                    *reinterpret_cast<float2*>(outf + (size_t)rowB * 128 + col) =
                        make_float2(c[mg][nf][2] + b0, c[mg][nf][3] + b1);
            }
        }
    }
}

// ---------------------------------------------------------------------------
// Launch: only the h_a branch matters — h_b in the reference is dead code.
// out = (relu(aggr_ba @ wl.T + x_a @ (w0+w1).T + biases)) @ out_w.T + out_b
// ---------------------------------------------------------------------------
extern "C" void kernel_launch(void* const* d_in, const int* in_sizes, int n_in,
                              void* d_out, int out_size) {
    const float* x_a     = (const float*)d_in[0];
    const int*   edge_ba = (const int*)d_in[3];
    const float* c1_w0_w = (const float*)d_in[10];
    const float* c1_w0_b = (const float*)d_in[11];
    const float* c1_wl_w = (const float*)d_in[12];
    const float* c1_wl_b = (const float*)d_in[13];
    const float* c1_w1_w = (const float*)d_in[14];
    const float* c1_w1_b = (const float*)d_in[15];
    const float* out_w   = (const float*)d_in[16];
    const float* out_b   = (const float*)d_in[17];
    float* out = (float*)d_out;

    u32 *ah, *al, *xh, *xl, *h1h, *h1l;
    int* headp;
    cudaGetSymbolAddress((void**)&ah, g_ah);
    cudaGetSymbolAddress((void**)&al, g_al);
    cudaGetSymbolAddress((void**)&xh, g_xh);
    cudaGetSymbolAddress((void**)&xl, g_xl);
    cudaGetSymbolAddress((void**)&h1h, g_h1h);
    cudaGetSymbolAddress((void**)&h1l, g_h1l);
    cudaGetSymbolAddress((void**)&headp, g_head);

    cudaFuncSetAttribute(tc_gemm,
                         cudaFuncAttributeMaxDynamicSharedMemorySize, SMB_TOT);

    // 1) head init via async memset (0xFFFFFFFF == -1)
    cudaMemsetAsync(headp, 0xFF, (size_t)Nn * sizeof(int));
    // 2) fused prep: build ∥ xsplit ∥ wprep
    prep_kernel<<<PB_TOTAL, 256>>>(edge_ba, x_a,
                                   c1_wl_w, c1_w0_w, c1_w1_w, out_w);
    // 3) gather-reduce (4 nodes per warp)
    aggregate_kernel<<<1563, 256>>>(x_a);
    // 4) h1 = relu(aggr @ Wl^T + x_a @ (W0+W1)^T + bias) -> split bf16
    tc_gemm<<<391, 256, SMB_TOT>>>(ah, al, xh, xl, 0, 1, 2,
                                   c1_wl_b, c1_w0_b, c1_w1_b,
                                   nullptr, h1h, h1l, 1, Nn);
    // 5) out = h1 @ Wout^T + out_b (fp32)
    tc_gemm<<<391, 256, SMB_TOT>>>(h1h, h1l, nullptr, nullptr, 2, 2, 1,
                                   out_b, nullptr, nullptr,
                                   out, nullptr, nullptr, 0, Nn);
}

// round 17
// speedup vs baseline: 1.4010x; 1.4010x over previous
#include <cuda_runtime.h>
#include <cuda_bf16.h>
#include <cstdint>

#define Nn 50000
#define Hh 128
#define Ee 500000

// fused prep kernel block ranges
#define PB_BUILD  1954                 // ceil(Ee/256)
#define PB_XSPLIT 3125                 // Nn*64/4/256
#define PB_WPREP  192                  // 3*16384/256
#define PB_TOTAL  (PB_BUILD + PB_XSPLIT + PB_WPREP)

typedef unsigned long long u64;
typedef unsigned int u32;

// ---------------------------------------------------------------------------
// Scratch (device globals: no allocation allowed)
// ---------------------------------------------------------------------------
__device__ int g_head[Nn];
__device__ u64 g_link[Ee];
__device__ u32 g_ah[(size_t)Nn * 64];   // aggr hi
__device__ u32 g_al[(size_t)Nn * 64];   // aggr lo
__device__ u32 g_xh[(size_t)Nn * 64];   // x_a hi
__device__ u32 g_xl[(size_t)Nn * 64];   // x_a lo
// Weights, TRANSPOSED row-major: Wt[k*128 + n] = W[n][k]. 0=Wl, 1=W0+W1, 2=Wout
__device__ unsigned short g_wt_hi[3][16384];
__device__ unsigned short g_wt_lo[3][16384];

// ---------------------------------------------------------------------------
// helpers
// ---------------------------------------------------------------------------
__device__ __forceinline__ u32 smem_u32(const void* p) {
    u32 a;
    asm("{ .reg .u64 t; cvta.to.shared.u64 t, %1; cvt.u32.u64 %0, t; }"
        : "=r"(a) : "l"(p));
    return a;
}
__device__ __forceinline__ void split2(float a, float b, u32& hi, u32& lo) {
    __nv_bfloat16 ha = __float2bfloat16(a), hb = __float2bfloat16(b);
    hi = (u32)__bfloat16_as_ushort(ha) | ((u32)__bfloat16_as_ushort(hb) << 16);
    __nv_bfloat16 la = __float2bfloat16(a - __bfloat162float(ha));
    __nv_bfloat16 lb = __float2bfloat16(b - __bfloat162float(hb));
    lo = (u32)__bfloat16_as_ushort(la) | ((u32)__bfloat16_as_ushort(lb) << 16);
}

#define LDMX4(r, addr) \
    asm volatile("ldmatrix.sync.aligned.m8n8.x4.shared.b16 {%0,%1,%2,%3}, [%4];" \
        : "=r"((r)[0]), "=r"((r)[1]), "=r"((r)[2]), "=r"((r)[3]) : "r"(addr))
#define LDMX4T(r, addr) \
    asm volatile("ldmatrix.sync.aligned.m8n8.x4.trans.shared.b16 {%0,%1,%2,%3}, [%4];" \
        : "=r"((r)[0]), "=r"((r)[1]), "=r"((r)[2]), "=r"((r)[3]) : "r"(addr))
#define MMA(c, a, b0, b1) \
    asm volatile("mma.sync.aligned.m16n8k16.row.col.f32.bf16.bf16.f32 " \
        "{%0,%1,%2,%3},{%4,%5,%6,%7},{%8,%9},{%0,%1,%2,%3};" \
        : "+f"((c)[0]), "+f"((c)[1]), "+f"((c)[2]), "+f"((c)[3]) \
        : "r"((a)[0]), "r"((a)[1]), "r"((a)[2]), "r"((a)[3]), "r"(b0), "r"(b1))
#define CPA16(dst, src) \
    asm volatile("cp.async.ca.shared.global [%0], [%1], 16;" \
                 :: "r"((u32)(dst)), "l"(src) : "memory")
#define CPA_COMMIT() asm volatile("cp.async.commit_group;" ::: "memory")
#define CPA_WAIT0()  asm volatile("cp.async.wait_group 0;" ::: "memory")

// ---------------------------------------------------------------------------
// Fused prep: build linked list ∥ split x_a ∥ weight transpose+split.
// ---------------------------------------------------------------------------
__global__ void prep_kernel(const int* __restrict__ edge,
                            const float* __restrict__ x,
                            const float* __restrict__ wl,
                            const float* __restrict__ w0,
                            const float* __restrict__ w1,
                            const float* __restrict__ wout) {
    int b = blockIdx.x;
    int tid = threadIdx.x;
    if (b < PB_BUILD) {
        int e = b * 256 + tid;
        if (e < Ee) {
            int dst = __ldg(edge + e);
            int src = __ldg(edge + Ee + e);
            int prev = atomicExch(&g_head[dst], e);
            g_link[e] = ((u64)(unsigned)src << 32) | (unsigned)prev;
        }
    } else if (b < PB_BUILD + PB_XSPLIT) {
        size_t t = (size_t)(b - PB_BUILD) * 256 + tid;
        const float4* xp = reinterpret_cast<const float4*>(x) + t * 2;
        float4 v0 = __ldg(xp);
        float4 v1 = __ldg(xp + 1);
        uint4 h, l;
        split2(v0.x, v0.y, h.x, l.x);
        split2(v0.z, v0.w, h.y, l.y);
        split2(v1.x, v1.y, h.z, l.z);
        split2(v1.z, v1.w, h.w, l.w);
        reinterpret_cast<uint4*>(g_xh)[t] = h;
        reinterpret_cast<uint4*>(g_xl)[t] = l;
    } else {
        int i = (b - PB_BUILD - PB_XSPLIT) * 256 + tid;
        int mat = i >> 14;
        int l = i & 16383;
        int k = l >> 7, n = l & 127;
        int src = n * 128 + k;
        float v = (mat == 0) ? __ldg(wl + src)
                : (mat == 1) ? __ldg(w0 + src) + __ldg(w1 + src)
                             : __ldg(wout + src);
        __nv_bfloat16 hb = __float2bfloat16(v);
        g_wt_hi[mat][l] = __bfloat16_as_ushort(hb);
        g_wt_lo[mat][l] =
            __bfloat16_as_ushort(__float2bfloat16(v - __bfloat162float(hb)));
    }
}

// ---------------------------------------------------------------------------
// Gather-reduce: TWO nodes per warp, interleaved chains (R13 verified).
// ---------------------------------------------------------------------------
__global__ void aggregate_kernel(const float* __restrict__ x) {
    int nb = blockIdx.x * 16 + (threadIdx.x >> 5) * 2;
    int lane = threadIdx.x & 31;
    float4 a0 = make_float4(0.f, 0.f, 0.f, 0.f);
    float4 a1 = make_float4(0.f, 0.f, 0.f, 0.f);
    int e0 = g_head[nb];
    int e1 = g_head[nb + 1];

    while (e0 != -1 && e1 != -1) {
        u64 p0 = __ldg(g_link + e0);
        u64 p1 = __ldg(g_link + e1);
        int s0 = (int)(p0 >> 32); e0 = (int)(unsigned)p0;
        int s1 = (int)(p1 >> 32); e1 = (int)(unsigned)p1;
        float4 v0 = *reinterpret_cast<const float4*>(x + (size_t)s0 * Hh + lane * 4);
        float4 v1 = *reinterpret_cast<const float4*>(x + (size_t)s1 * Hh + lane * 4);
        a0.x += v0.x; a0.y += v0.y; a0.z += v0.z; a0.w += v0.w;
        a1.x += v1.x; a1.y += v1.y; a1.z += v1.z; a1.w += v1.w;
    }
    while (e0 != -1) {
        u64 p0 = __ldg(g_link + e0);
        int s0 = (int)(p0 >> 32); e0 = (int)(unsigned)p0;
        float4 v0 = *reinterpret_cast<const float4*>(x + (size_t)s0 * Hh + lane * 4);
        a0.x += v0.x; a0.y += v0.y; a0.z += v0.z; a0.w += v0.w;
    }
    while (e1 != -1) {
        u64 p1 = __ldg(g_link + e1);
        int s1 = (int)(p1 >> 32); e1 = (int)(unsigned)p1;
        float4 v1 = *reinterpret_cast<const float4*>(x + (size_t)s1 * Hh + lane * 4);
        a1.x += v1.x; a1.y += v1.y; a1.z += v1.z; a1.w += v1.w;
    }

    u32 h0, l0, h1, l1;
    split2(a0.x, a0.y, h0, l0);
    split2(a0.z, a0.w, h1, l1);
    size_t o0 = (size_t)nb * 64 + lane * 2;
    g_ah[o0] = h0; g_ah[o0 + 1] = h1;
    g_al[o0] = l0; g_al[o0 + 1] = l1;

    split2(a1.x, a1.y, h0, l0);
    split2(a1.z, a1.w, h1, l1);
    size_t o1 = (size_t)(nb + 1) * 64 + lane * 2;
    g_ah[o1] = h0; g_ah[o1 + 1] = h1;
    g_al[o1] = l0; g_al[o1 + 1] = l1;
}

// ---------------------------------------------------------------------------
// FUSED two-layer tensor-core GEMM, one 128-row tile per block:
//  phase 1 (R13 pipeline): acc = aggr@Wl^T + x@(W0+W1)^T      (K=256)
//  h1 = relu(acc + bias1) -> split bf16 hi/lo -> SMEM planes (272B pitch)
//  phase 2 (R15 W-streaming): out = h1@Wout^T + out_b -> fp32 global
// 256 threads = 8 warps (warp tile 32m x 64n).
// ---------------------------------------------------------------------------
#define SMB_BIAS1 0        // 512 B  (bl+b0+b1)
#define SMB_BIAS2 512      // 512 B  (out_b)
// phase 1 regions
#define SMB_A0    1024     // A buf0: hi 6144 + lo 6144
#define SMB_A1    13312    // A buf1
#define ABUF_LO   6144
#define SMB_WH    25600    // W resident hi: 128 x 272
#define SMB_WL    60416    // W resident lo
// phase 2 regions (overlap phase-1's; used only after barrier)
#define SMB_H     1024     // h1 hi plane: 128 x 272
#define SMB_HL    35840    // h1 lo plane
#define SMB_WB0   70656    // W chunk buf0: hi 4352 + lo 4352
#define SMB_WB1   79360    // W chunk buf1
#define WCH_LO    4352
#define SMB_TOT   95232
#define APITCH    48
#define WPITCH    272
#define HPITCH    272

__global__ __launch_bounds__(256, 2) void tc_fused(
    const u32* __restrict__ A0h, const u32* __restrict__ A0l,
    const u32* __restrict__ A1h, const u32* __restrict__ A1l,
    const float* __restrict__ b1a, const float* __restrict__ b1b,
    const float* __restrict__ b1c, const float* __restrict__ b2,
    float* __restrict__ outf, int M)
{
    extern __shared__ __align__(16) char smem[];
    const u32 sb = smem_u32(smem);
    float* bias1_s = reinterpret_cast<float*>(smem + SMB_BIAS1);
    float* bias2_s = reinterpret_cast<float*>(smem + SMB_BIAS2);

    const int tid = threadIdx.x;
    const int w = tid >> 5, lane = tid & 31;
    const int mw = (w & 3) * 32, nw = (w >> 2) * 64;
    const int bm = blockIdx.x * 128;

    // boundary block: pre-zero both A buffers (cp.async skips invalid rows)
    if (bm + 128 > M) {
        #pragma unroll
        for (int q = 0; q < 6; q++)
            reinterpret_cast<uint4*>(smem + SMB_A0)[q * 256 + tid] =
                make_uint4(0, 0, 0, 0);
    }
    if (tid < 128) {
        bias1_s[tid] = __ldg(b1a + tid) + __ldg(b1b + tid) + __ldg(b1c + tid);
        bias2_s[tid] = __ldg(b2 + tid);
    }

    // lane-constant address pieces
    const u32 aoff  = (u32)((mw + (lane & 15)) * APITCH + (lane >> 4) * 16);
    const u32 hoff  = (u32)((mw + (lane & 15)) * HPITCH + (lane >> 4) * 16);
    const int wg = lane >> 3, wi = lane & 7;
    const u32 wkoff = (u32)(((wg & 1) * 8 + wi) * WPITCH);
    const u32 wnoff = (u32)((nw + (wg >> 1) * 8) * 2);

    const int ar = tid >> 1, ahalf = tid & 1;
    const bool avalid = (bm + ar) < M;
    const u32 adst_off = (u32)(ar * APITCH + ahalf * 16);
    // phase-2 W-chunk stage mapping
    const int wkk = tid >> 4, wc16 = tid & 15;
    const u32 w2dst = (u32)(wkk * WPITCH + wc16 * 16);

    float c[2][8][4];
    #pragma unroll
    for (int mg = 0; mg < 2; mg++)
        #pragma unroll
        for (int nf = 0; nf < 8; nf++)
            #pragma unroll
            for (int q = 0; q < 4; q++) c[mg][nf][q] = 0.f;

    // =================== PHASE 1: K=256 (2 segments) ===================
    #pragma unroll 1
    for (int seg = 0; seg < 2; seg++) {
        const u32* Ah = seg ? A1h : A0h;
        const u32* Al = seg ? A1l : A0l;
        const int mat = seg;   // 0 = Wl, 1 = W0+W1

        __syncthreads();

        {   // async stage W hi/lo (full segment, resident)
            const char* sh = reinterpret_cast<const char*>(g_wt_hi[mat]);
            const char* sl = reinterpret_cast<const char*>(g_wt_lo[mat]);
            #pragma unroll
            for (int q = 0; q < 8; q++) {
                int u = q * 256 + tid;
                int kk = u >> 4, c16 = u & 15;
                u32 d = (u32)(kk * WPITCH + c16 * 16);
                CPA16(sb + SMB_WH + d, sh + (size_t)u * 16);
                CPA16(sb + SMB_WL + d, sl + (size_t)u * 16);
            }
        }
        if (avalid) {
            size_t su = (size_t)(bm + ar) * 16 + ahalf;
            CPA16(sb + SMB_A0 + adst_off,
                  reinterpret_cast<const char*>(Ah) + su * 16);
            CPA16(sb + SMB_A0 + ABUF_LO + adst_off,
                  reinterpret_cast<const char*>(Al) + su * 16);
        }
        CPA_COMMIT();

        #pragma unroll 1
        for (int kc = 0; kc < 8; kc++) {
            CPA_WAIT0();
            __syncthreads();

            if (kc < 7) {
                u32 dstb = sb + (((kc + 1) & 1) ? SMB_A1 : SMB_A0);
                if (avalid) {
                    size_t su = (size_t)(bm + ar) * 16 + (kc + 1) * 2 + ahalf;
                    CPA16(dstb + adst_off,
                          reinterpret_cast<const char*>(Ah) + su * 16);
                    CPA16(dstb + ABUF_LO + adst_off,
                          reinterpret_cast<const char*>(Al) + su * 16);
                }
                CPA_COMMIT();
            }

            const u32 abase = sb + ((kc & 1) ? SMB_A1 : SMB_A0);
            u32 ah[2][4], al_[2][4];
            #pragma unroll
            for (int mg = 0; mg < 2; mg++) {
                LDMX4(ah[mg],  abase + aoff + mg * 16 * APITCH);
                LDMX4(al_[mg], abase + ABUF_LO + aoff + mg * 16 * APITCH);
            }
            u32 bw[4][4];
            const u32 wko = (u32)(kc * 16 * WPITCH) + wkoff;
            #pragma unroll
            for (int nf = 0; nf < 4; nf++)
                LDMX4T(bw[nf], sb + SMB_WH + wko + wnoff + nf * 32);
            #pragma unroll
            for (int mg = 0; mg < 2; mg++)
                #pragma unroll
                for (int nf = 0; nf < 4; nf++) {
                    MMA(c[mg][2 * nf],     ah[mg],  bw[nf][0], bw[nf][1]);
                    MMA(c[mg][2 * nf + 1], ah[mg],  bw[nf][2], bw[nf][3]);
                    MMA(c[mg][2 * nf],     al_[mg], bw[nf][0], bw[nf][1]);
                    MMA(c[mg][2 * nf + 1], al_[mg], bw[nf][2], bw[nf][3]);
                }
            #pragma unroll
            for (int nf = 0; nf < 4; nf++)
                LDMX4T(bw[nf], sb + SMB_WL + wko + wnoff + nf * 32);
            #pragma unroll
            for (int mg = 0; mg < 2; mg++)
                #pragma unroll
                for (int nf = 0; nf < 4; nf++) {
                    MMA(c[mg][2 * nf],     ah[mg], bw[nf][0], bw[nf][1]);
                    MMA(c[mg][2 * nf + 1], ah[mg], bw[nf][2], bw[nf][3]);
                }
        }
    }

    // ---- h1 = relu(acc + bias1), split bf16 -> SMEM planes ----
    __syncthreads();   // all phase-1 compute done; A/W regions now reusable
    {
        const int r0 = (lane >> 2);
        const int cb = 2 * (lane & 3);
        #pragma unroll
        for (int mg = 0; mg < 2; mg++) {
            #pragma unroll
            for (int nf = 0; nf < 8; nf++) {
                int col = nw + nf * 8 + cb;
                int rA = mw + mg * 16 + r0;
                int rB = rA + 8;
                float bb0 = bias1_s[col], bb1 = bias1_s[col + 1];
                u32 hi, lo;
                split2(fmaxf(c[mg][nf][0] + bb0, 0.f),
                       fmaxf(c[mg][nf][1] + bb1, 0.f), hi, lo);
                *reinterpret_cast<u32*>(smem + SMB_H  + rA * HPITCH + col * 2) = hi;
                *reinterpret_cast<u32*>(smem + SMB_HL + rA * HPITCH + col * 2) = lo;
                split2(fmaxf(c[mg][nf][2] + bb0, 0.f),
                       fmaxf(c[mg][nf][3] + bb1, 0.f), hi, lo);
                *reinterpret_cast<u32*>(smem + SMB_H  + rB * HPITCH + col * 2) = hi;
                *reinterpret_cast<u32*>(smem + SMB_HL + rB * HPITCH + col * 2) = lo;
            }
        }
    }
    // stage Wout chunk 0
    {
        size_t wsrc = (size_t)wkk * 256 + wc16 * 16;
        CPA16(sb + SMB_WB0 + w2dst,
              reinterpret_cast<const char*>(g_wt_hi[2]) + wsrc);
        CPA16(sb + SMB_WB0 + WCH_LO + w2dst,
              reinterpret_cast<const char*>(g_wt_lo[2]) + wsrc);
    }
    CPA_COMMIT();
    __syncthreads();   // H planes visible to all warps

    // =================== PHASE 2: out = h1 @ Wout^T ===================
    #pragma unroll
    for (int mg = 0; mg < 2; mg++)
        #pragma unroll
        for (int nf = 0; nf < 8; nf++)
            #pragma unroll
            for (int q = 0; q < 4; q++) c[mg][nf][q] = 0.f;

    #pragma unroll 1
    for (int kc = 0; kc < 8; kc++) {
        CPA_WAIT0();
        __syncthreads();

        if (kc < 7) {
            u32 dstb = sb + (((kc + 1) & 1) ? SMB_WB1 : SMB_WB0);
            size_t wsrc = (size_t)((kc + 1) * 16 + wkk) * 256 + wc16 * 16;
            CPA16(dstb + w2dst,
                  reinterpret_cast<const char*>(g_wt_hi[2]) + wsrc);
            CPA16(dstb + WCH_LO + w2dst,
                  reinterpret_cast<const char*>(g_wt_lo[2]) + wsrc);
            CPA_COMMIT();
        }

        const u32 wb_ = sb + ((kc & 1) ? SMB_WB1 : SMB_WB0);
        u32 ah[2][4], al_[2][4];
        #pragma unroll
        for (int mg = 0; mg < 2; mg++) {
            LDMX4(ah[mg],  sb + SMB_H  + hoff + kc * 32 + mg * 16 * HPITCH);
            LDMX4(al_[mg], sb + SMB_HL + hoff + kc * 32 + mg * 16 * HPITCH);
        }
        u32 bw[4][4];
        #pragma unroll
        for (int nf = 0; nf < 4; nf++)
            LDMX4T(bw[nf], wb_ + wkoff + wnoff + nf * 32);
        #pragma unroll
        for (int mg = 0; mg < 2; mg++)
            #pragma unroll
            for (int nf = 0; nf < 4; nf++) {
                MMA(c[mg][2 * nf],     ah[mg],  bw[nf][0], bw[nf][1]);
                MMA(c[mg][2 * nf + 1], ah[mg],  bw[nf][2], bw[nf][3]);
                MMA(c[mg][2 * nf],     al_[mg], bw[nf][0], bw[nf][1]);
                MMA(c[mg][2 * nf + 1], al_[mg], bw[nf][2], bw[nf][3]);
            }
        #pragma unroll
        for (int nf = 0; nf < 4; nf++)
            LDMX4T(bw[nf], wb_ + WCH_LO + wkoff + wnoff + nf * 32);
        #pragma unroll
        for (int mg = 0; mg < 2; mg++)
            #pragma unroll
            for (int nf = 0; nf < 4; nf++) {
                MMA(c[mg][2 * nf],     ah[mg], bw[nf][0], bw[nf][1]);
                MMA(c[mg][2 * nf + 1], ah[mg], bw[nf][2], bw[nf][3]);
            }
    }

    // ---- final epilogue: out = c + out_b (fp32) ----
    {
        const int r0 = (lane >> 2);
        const int cb = 2 * (lane & 3);
        #pragma unroll
        for (int mg = 0; mg < 2; mg++) {
            #pragma unroll
            for (int nf = 0; nf < 8; nf++) {
                int col = nw + nf * 8 + cb;
                int rowA = bm + mw + mg * 16 + r0;
                int rowB = rowA + 8;
                float bb0 = bias2_s[col], bb1 = bias2_s[col + 1];
                if (rowA < M)
                    *reinterpret_cast<float2*>(outf + (size_t)rowA * 128 + col) =
                        make_float2(c[mg][nf][0] + bb0, c[mg][nf][1] + bb1);
                if (rowB < M)
                    *reinterpret_cast<float2*>(outf + (size_t)rowB * 128 + col) =
                        make_float2(c[mg][nf][2] + bb0, c[mg][nf][3] + bb1);
            }
        }
    }
}

// ---------------------------------------------------------------------------
// Launch: only the h_a branch matters — h_b in the reference is dead code.
// out = (relu(aggr_ba @ wl.T + x_a @ (w0+w1).T + biases)) @ out_w.T + out_b
// ---------------------------------------------------------------------------
extern "C" void kernel_launch(void* const* d_in, const int* in_sizes, int n_in,
                              void* d_out, int out_size) {
    const float* x_a     = (const float*)d_in[0];
    const int*   edge_ba = (const int*)d_in[3];
    const float* c1_w0_w = (const float*)d_in[10];
    const float* c1_w0_b = (const float*)d_in[11];
    const float* c1_wl_w = (const float*)d_in[12];
    const float* c1_wl_b = (const float*)d_in[13];
    const float* c1_w1_w = (const float*)d_in[14];
    const float* c1_w1_b = (const float*)d_in[15];
    const float* out_w   = (const float*)d_in[16];
    const float* out_b   = (const float*)d_in[17];
    float* out = (float*)d_out;

    u32 *ah, *al, *xh, *xl;
    int* headp;
    cudaGetSymbolAddress((void**)&ah, g_ah);
    cudaGetSymbolAddress((void**)&al, g_al);
    cudaGetSymbolAddress((void**)&xh, g_xh);
    cudaGetSymbolAddress((void**)&xl, g_xl);
    cudaGetSymbolAddress((void**)&headp, g_head);

    cudaFuncSetAttribute(tc_fused,
                         cudaFuncAttributeMaxDynamicSharedMemorySize, SMB_TOT);

    // 1) head init via async memset (0xFFFFFFFF == -1)
    cudaMemsetAsync(headp, 0xFF, (size_t)Nn * sizeof(int));
    // 2) fused prep: build ∥ xsplit ∥ wprep
    prep_kernel<<<PB_TOTAL, 256>>>(edge_ba, x_a,
                                   c1_wl_w, c1_w0_w, c1_w1_w, out_w);
    // 3) gather-reduce (2 nodes per warp)
    aggregate_kernel<<<3125, 256>>>(x_a);
    // 4) fused both layers: h1 in SMEM, out to global
    tc_fused<<<391, 256, SMB_TOT>>>(ah, al, xh, xl,
                                    c1_wl_b, c1_w0_b, c1_w1_b, out_b,
                                    out, Nn);
}